// round 1
// baseline (speedup 1.0000x reference)
#include <cuda_runtime.h>
#include <math.h>

#define NB   4
#define CIN  256
#define C8D  32
#define NPIX 4096

// Scratch (device globals: allocation-free per harness rules)
__device__ float g_q[NB * C8D * NPIX];
__device__ float g_k[NB * C8D * NPIX];
__device__ float g_v[NB * CIN * NPIX];

// ---------------------------------------------------------------------------
// q/k projection: q[b,o,n] = sum_c Wq[o,c] x[b,c,n] + bq[o]   (o < 32)
// grid (32, 4), block 128. Weights cached in dynamic SMEM (64KB+).
// ---------------------------------------------------------------------------
__global__ __launch_bounds__(128) void qk_proj_kernel(
    const float* __restrict__ x,
    const float* __restrict__ Wq, const float* __restrict__ bq,
    const float* __restrict__ Wk, const float* __restrict__ bk)
{
    extern __shared__ float sm[];
    float* sWq = sm;            // 32*256
    float* sWk = sm + 8192;     // 32*256
    float* sbq = sm + 16384;    // 32
    float* sbk = sm + 16416;    // 32

    int t = threadIdx.x;
    for (int i = t; i < 8192; i += 128) { sWq[i] = Wq[i]; sWk[i] = Wk[i]; }
    if (t < 32) { sbq[t] = bq[t]; sbk[t] = bk[t]; }
    __syncthreads();

    int b = blockIdx.y;
    int n = blockIdx.x * 128 + t;
    const float* xp = x + ((size_t)b * CIN) * NPIX + n;

    float accq[32], acck[32];
#pragma unroll
    for (int o = 0; o < 32; o++) { accq[o] = sbq[o]; acck[o] = sbk[o]; }

    for (int c = 0; c < 256; c += 4) {
        float x0 = xp[(c + 0) * NPIX];
        float x1 = xp[(c + 1) * NPIX];
        float x2 = xp[(c + 2) * NPIX];
        float x3 = xp[(c + 3) * NPIX];
#pragma unroll
        for (int o = 0; o < 32; o++) {
            float4 wq = *(const float4*)&sWq[o * 256 + c];
            accq[o] += wq.x * x0 + wq.y * x1 + wq.z * x2 + wq.w * x3;
            float4 wk = *(const float4*)&sWk[o * 256 + c];
            acck[o] += wk.x * x0 + wk.y * x1 + wk.z * x2 + wk.w * x3;
        }
    }

    size_t base = ((size_t)b * C8D) * NPIX + n;
#pragma unroll
    for (int o = 0; o < 32; o++) {
        g_q[base + (size_t)o * NPIX] = accq[o];
        g_k[base + (size_t)o * NPIX] = acck[o];
    }
}

// ---------------------------------------------------------------------------
// v projection: v[b,o,n] = sum_c Wv[o,c] x[b,c,n] + bv[o]
// 128x128 tile GEMM, K-tile 16, 8x8 per thread. grid (32, 2, 4), block 256.
// ---------------------------------------------------------------------------
__global__ __launch_bounds__(256) void v_proj_kernel(
    const float* __restrict__ x,
    const float* __restrict__ Wv, const float* __restrict__ bv)
{
    __shared__ float As[16][132];   // As[kc][o] (transposed Wv chunk)
    __shared__ float Bs[16][128];   // Bs[kc][n]

    int b  = blockIdx.z;
    int o0 = blockIdx.y * 128;
    int n0 = blockIdx.x * 128;
    int t  = threadIdx.x;
    int tx = t & 15, ty = t >> 4;
    const float* xb = x + ((size_t)b * CIN) * NPIX;

    float acc[8][8];
#pragma unroll
    for (int i = 0; i < 8; i++)
#pragma unroll
        for (int j = 0; j < 8; j++) acc[i][j] = 0.0f;

    for (int k0 = 0; k0 < 256; k0 += 16) {
        {
            int o = t >> 1, cb = (t & 1) * 8;
            const float* wp = Wv + (size_t)(o0 + o) * 256 + k0 + cb;
            float4 w0 = *(const float4*)wp;
            float4 w1 = *(const float4*)(wp + 4);
            As[cb + 0][o] = w0.x; As[cb + 1][o] = w0.y;
            As[cb + 2][o] = w0.z; As[cb + 3][o] = w0.w;
            As[cb + 4][o] = w1.x; As[cb + 5][o] = w1.y;
            As[cb + 6][o] = w1.z; As[cb + 7][o] = w1.w;
        }
#pragma unroll
        for (int r = 0; r < 2; r++) {
            int f  = t + r * 256;
            int kc = f >> 5, c4 = f & 31;
            *(float4*)&Bs[kc][c4 * 4] =
                *(const float4*)&xb[(size_t)(k0 + kc) * NPIX + n0 + c4 * 4];
        }
        __syncthreads();

#pragma unroll
        for (int kc = 0; kc < 16; kc++) {
            float4 a0 = *(const float4*)&As[kc][ty * 8];
            float4 a1 = *(const float4*)&As[kc][ty * 8 + 4];
            float4 b0 = *(const float4*)&Bs[kc][tx * 4];
            float4 b1 = *(const float4*)&Bs[kc][64 + tx * 4];
            float av[8] = {a0.x, a0.y, a0.z, a0.w, a1.x, a1.y, a1.z, a1.w};
            float bw[8] = {b0.x, b0.y, b0.z, b0.w, b1.x, b1.y, b1.z, b1.w};
#pragma unroll
            for (int i = 0; i < 8; i++)
#pragma unroll
                for (int j = 0; j < 8; j++) acc[i][j] += av[i] * bw[j];
        }
        __syncthreads();
    }

#pragma unroll
    for (int i = 0; i < 8; i++) {
        int o = o0 + ty * 8 + i;
        float bias = bv[o];
        size_t base = ((size_t)b * CIN + o) * NPIX;
        float4 w;
        w.x = acc[i][0] + bias; w.y = acc[i][1] + bias;
        w.z = acc[i][2] + bias; w.w = acc[i][3] + bias;
        *(float4*)&g_v[base + n0 + tx * 4] = w;
        w.x = acc[i][4] + bias; w.y = acc[i][5] + bias;
        w.z = acc[i][6] + bias; w.w = acc[i][7] + bias;
        *(float4*)&g_v[base + n0 + 64 + tx * 4] = w;
    }
}

// ---------------------------------------------------------------------------
// Fused flash attention + epilogue:
//   S = q^T k (d=32), online softmax over m, O += V P^T, out = gamma*O/l + x
// grid (64, 4), block 256, ~105KB dynamic SMEM, 2 CTA/SM.
// ---------------------------------------------------------------------------
__global__ __launch_bounds__(256, 2) void attn_kernel(
    const float* __restrict__ x, const float* __restrict__ gamma,
    float* __restrict__ out)
{
    extern __shared__ float sm[];
    float* Qs   = sm;                 // [32][68]
    float* Ks   = Qs + 32 * 68;       // [32][68]
    float* Ps   = Ks + 32 * 68;       // [64][68]
    float* Vs   = Ps + 64 * 68;       // [256][68]
    float* mrun = Vs + 256 * 68;      // [64]
    float* lrun = mrun + 64;          // [64]
    float* alph = lrun + 64;          // [64]

    int t  = threadIdx.x;
    int b  = blockIdx.y;
    int n0 = blockIdx.x * 64;
    const float* qb = g_q + ((size_t)b * C8D) * NPIX;
    const float* kb = g_k + ((size_t)b * C8D) * NPIX;
    const float* vb = g_v + ((size_t)b * CIN) * NPIX;

    // load Q tile [32][64]
    for (int f = t; f < C8D * 16; f += 256) {
        int d = f >> 4, c4 = f & 15;
        *(float4*)&Qs[d * 68 + c4 * 4] =
            *(const float4*)&qb[(size_t)d * NPIX + n0 + c4 * 4];
    }
    if (t < 64) { mrun[t] = -INFINITY; lrun[t] = 0.0f; }

    float O[8][8];
#pragma unroll
    for (int i = 0; i < 8; i++)
#pragma unroll
        for (int j = 0; j < 8; j++) O[i][j] = 0.0f;

    int sx = t & 15, sy = t >> 4;   // S-phase: m / n tile coords
    int ox = t & 7,  oy = t >> 3;   // O-phase: n-group / c-group
    __syncthreads();

    for (int mt = 0; mt < 64; mt++) {
        int m0 = mt * 64;
        // load K [32][64] and V [256][64]
        for (int f = t; f < C8D * 16; f += 256) {
            int d = f >> 4, c4 = f & 15;
            *(float4*)&Ks[d * 68 + c4 * 4] =
                *(const float4*)&kb[(size_t)d * NPIX + m0 + c4 * 4];
        }
        for (int f = t; f < CIN * 16; f += 256) {
            int c = f >> 4, c4 = f & 15;
            *(float4*)&Vs[c * 68 + c4 * 4] =
                *(const float4*)&vb[(size_t)c * NPIX + m0 + c4 * 4];
        }
        __syncthreads();

        // ---- S = Q^T K : each thread 4x4 of S[64][64] ----
        float s[4][4];
#pragma unroll
        for (int r = 0; r < 4; r++)
#pragma unroll
            for (int c = 0; c < 4; c++) s[r][c] = 0.0f;
#pragma unroll
        for (int d = 0; d < 32; d++) {
            float4 q  = *(const float4*)&Qs[d * 68 + sy * 4];
            float4 k4 = *(const float4*)&Ks[d * 68 + sx * 4];
            s[0][0] += q.x * k4.x; s[0][1] += q.x * k4.y;
            s[0][2] += q.x * k4.z; s[0][3] += q.x * k4.w;
            s[1][0] += q.y * k4.x; s[1][1] += q.y * k4.y;
            s[1][2] += q.y * k4.z; s[1][3] += q.y * k4.w;
            s[2][0] += q.z * k4.x; s[2][1] += q.z * k4.y;
            s[2][2] += q.z * k4.z; s[2][3] += q.z * k4.w;
            s[3][0] += q.w * k4.x; s[3][1] += q.w * k4.y;
            s[3][2] += q.w * k4.z; s[3][3] += q.w * k4.w;
        }

        // ---- online softmax per row (16 lanes per row) ----
#pragma unroll
        for (int r = 0; r < 4; r++) {
            int n = sy * 4 + r;
            float mx = fmaxf(fmaxf(s[r][0], s[r][1]), fmaxf(s[r][2], s[r][3]));
#pragma unroll
            for (int off = 8; off >= 1; off >>= 1)
                mx = fmaxf(mx, __shfl_xor_sync(0xffffffffu, mx, off));
            float mold = mrun[n];
            float mnew = fmaxf(mold, mx);
            float p0 = __expf(s[r][0] - mnew);
            float p1 = __expf(s[r][1] - mnew);
            float p2 = __expf(s[r][2] - mnew);
            float p3 = __expf(s[r][3] - mnew);
            float sum = (p0 + p1) + (p2 + p3);
#pragma unroll
            for (int off = 8; off >= 1; off >>= 1)
                sum += __shfl_xor_sync(0xffffffffu, sum, off);
            float4 pq = make_float4(p0, p1, p2, p3);
            *(float4*)&Ps[n * 68 + sx * 4] = pq;
            if (sx == 0) {
                float a = __expf(mold - mnew);
                lrun[n] = lrun[n] * a + sum;
                mrun[n] = mnew;
                alph[n] = a;
            }
        }
        __syncthreads();

        // ---- O rescale + O += V P^T : thread owns c = oy+32*cc, n = ox+8*i
#pragma unroll
        for (int i = 0; i < 8; i++) {
            float a = alph[ox + 8 * i];
#pragma unroll
            for (int cc = 0; cc < 8; cc++) O[cc][i] *= a;
        }
#pragma unroll 4
        for (int j = 0; j < 64; j += 2) {
            float2 pv[8];
#pragma unroll
            for (int i = 0; i < 8; i++)
                pv[i] = *(const float2*)&Ps[(ox + 8 * i) * 68 + j];
            float2 vv[8];
#pragma unroll
            for (int cc = 0; cc < 8; cc++)
                vv[cc] = *(const float2*)&Vs[(oy + 32 * cc) * 68 + j];
#pragma unroll
            for (int cc = 0; cc < 8; cc++)
#pragma unroll
                for (int i = 0; i < 8; i++)
                    O[cc][i] += vv[cc].x * pv[i].x + vv[cc].y * pv[i].y;
        }
        __syncthreads();
    }

    // ---- epilogue: out = gamma * O/l + x ----
    float g = gamma[0];
#pragma unroll
    for (int i = 0; i < 8; i++) {
        int nl = ox + 8 * i;
        float linv = 1.0f / lrun[nl];
        int n = n0 + nl;
#pragma unroll
        for (int cc = 0; cc < 8; cc++) {
            int c = oy + 32 * cc;
            size_t idx = ((size_t)b * CIN + c) * NPIX + n;
            out[idx] = g * (O[cc][i] * linv) + x[idx];
        }
    }
}

// ---------------------------------------------------------------------------
extern "C" void kernel_launch(void* const* d_in, const int* in_sizes, int n_in,
                              void* d_out, int out_size)
{
    const float* x     = (const float*)d_in[0];
    const float* Wq    = (const float*)d_in[1];
    const float* bq    = (const float*)d_in[2];
    const float* Wk    = (const float*)d_in[3];
    const float* bk    = (const float*)d_in[4];
    const float* Wv    = (const float*)d_in[5];
    const float* bv    = (const float*)d_in[6];
    const float* gamma = (const float*)d_in[7];
    float* out = (float*)d_out;

    const int QK_SMEM   = (2 * 32 * 256 + 64) * 4;                 // 65792 B
    const int ATTN_SMEM = (32*68 + 32*68 + 64*68 + 256*68 + 192) * 4; // 105216 B

    cudaFuncSetAttribute(qk_proj_kernel,
                         cudaFuncAttributeMaxDynamicSharedMemorySize, QK_SMEM);
    cudaFuncSetAttribute(attn_kernel,
                         cudaFuncAttributeMaxDynamicSharedMemorySize, ATTN_SMEM);

    qk_proj_kernel<<<dim3(NPIX / 128, NB), 128, QK_SMEM>>>(x, Wq, bq, Wk, bk);
    v_proj_kernel<<<dim3(NPIX / 128, CIN / 128, NB), 256>>>(x, Wv, bv);
    attn_kernel<<<dim3(NPIX / 64, NB), 256, ATTN_SMEM>>>(x, gamma, out);
}

// round 4
// speedup vs baseline: 4.2702x; 4.2702x over previous
#include <cuda_runtime.h>
#include <math.h>

#define NB   4
#define CIN  256
#define C8D  32
#define NPIX 4096

// Scratch (device globals: allocation-free per harness rules).
// Values stored pre-rounded to tf32 bit patterns.
__device__ float g_q[NB * C8D * NPIX];
__device__ float g_k[NB * C8D * NPIX];
__device__ float g_v[NB * CIN * NPIX];

__device__ __forceinline__ unsigned f2tf32(float x) {
    unsigned u;
    asm("cvt.rna.tf32.f32 %0, %1;" : "=r"(u) : "f"(x));
    return u;
}

__device__ __forceinline__ void mma_tf32(float* d, const unsigned* a, const unsigned* b) {
    asm volatile(
        "mma.sync.aligned.m16n8k8.row.col.f32.tf32.tf32.f32 "
        "{%0,%1,%2,%3}, {%4,%5,%6,%7}, {%8,%9}, {%0,%1,%2,%3};"
        : "+f"(d[0]), "+f"(d[1]), "+f"(d[2]), "+f"(d[3])
        : "r"(a[0]), "r"(a[1]), "r"(a[2]), "r"(a[3]), "r"(b[0]), "r"(b[1]));
}

// ---------------------------------------------------------------------------
// Merged projection: [Wv(256); Wq(32); Wk(32)] @ x[b] -> g_v, g_q, g_k
// 64x128 tiles, K-chunk 16. grid (32, 5, 4), block 256.
// ---------------------------------------------------------------------------
__global__ __launch_bounds__(256) void proj_kernel(
    const float* __restrict__ x,
    const float* __restrict__ Wq, const float* __restrict__ bq,
    const float* __restrict__ Wk, const float* __restrict__ bk,
    const float* __restrict__ Wv, const float* __restrict__ bv)
{
    __shared__ float As[16][68];    // [kc][row]
    __shared__ float Bs[16][128];   // [kc][n]

    int b  = blockIdx.z;
    int r0 = blockIdx.y * 64;
    int n0 = blockIdx.x * 128;
    int t  = threadIdx.x;
    int tx = t & 31, ty = t >> 5;   // n-group (4 cols), m-group (8 rows)
    const float* xb = x + ((size_t)b * CIN) * NPIX;

    float acc[8][4];
#pragma unroll
    for (int i = 0; i < 8; i++)
#pragma unroll
        for (int j = 0; j < 4; j++) acc[i][j] = 0.0f;

    for (int k0 = 0; k0 < 256; k0 += 16) {
        // A: weight rows r0..r0+63, k-slice [k0, k0+16)
        {
            int row = t >> 2;
            int kc  = (t & 3) * 4;
            int gr  = r0 + row;
            const float* wp = (gr < 256) ? (Wv + (size_t)gr * 256)
                            : (gr < 288) ? (Wq + (size_t)(gr - 256) * 256)
                                         : (Wk + (size_t)(gr - 288) * 256);
            float4 w = *(const float4*)(wp + k0 + kc);
            As[kc + 0][row] = w.x; As[kc + 1][row] = w.y;
            As[kc + 2][row] = w.z; As[kc + 3][row] = w.w;
        }
        // B: x rows k0..k0+15, cols n0..n0+127
#pragma unroll
        for (int i = 0; i < 2; i++) {
            int idx = t + 256 * i;
            int kc = idx >> 5, j = idx & 31;
            *(float4*)&Bs[kc][j * 4] =
                *(const float4*)&xb[(size_t)(k0 + kc) * NPIX + n0 + j * 4];
        }
        __syncthreads();

#pragma unroll
        for (int kc = 0; kc < 16; kc++) {
            float a[8];
#pragma unroll
            for (int i = 0; i < 8; i++) a[i] = As[kc][ty * 8 + i];
            float4 bb = *(const float4*)&Bs[kc][tx * 4];
#pragma unroll
            for (int i = 0; i < 8; i++) {
                acc[i][0] += a[i] * bb.x;
                acc[i][1] += a[i] * bb.y;
                acc[i][2] += a[i] * bb.z;
                acc[i][3] += a[i] * bb.w;
            }
        }
        __syncthreads();
    }

#pragma unroll
    for (int i = 0; i < 8; i++) {
        int gr = r0 + ty * 8 + i;
        float bias;
        float* op;
        if (gr < 256)      { bias = bv[gr];       op = g_v + ((size_t)b * CIN + gr) * NPIX; }
        else if (gr < 288) { bias = bq[gr - 256]; op = g_q + ((size_t)b * C8D + gr - 256) * NPIX; }
        else               { bias = bk[gr - 288]; op = g_k + ((size_t)b * C8D + gr - 288) * NPIX; }
        float4 o;
        o.x = __uint_as_float(f2tf32(acc[i][0] + bias));
        o.y = __uint_as_float(f2tf32(acc[i][1] + bias));
        o.z = __uint_as_float(f2tf32(acc[i][2] + bias));
        o.w = __uint_as_float(f2tf32(acc[i][3] + bias));
        *(float4*)&op[n0 + tx * 4] = o;
    }
}

// ---------------------------------------------------------------------------
// Flash attention, tf32 mma. BQ=128 queries/CTA, BK=64 keys/iter.
// grid (32, 4), block 256 (8 warps), ~133KB smem, 1 CTA/SM, single wave.
// S phase: warp w owns rows [16w,16w+16), full 64 cols.
// PV phase: warp (wr=w>>1, wc=w&1) owns c in [64wr,64wr+64), n in [64wc,64wc+64).
// ---------------------------------------------------------------------------
#define QS_S 36
#define KS_S 72
#define VS_S 68
#define PS_S 136

__global__ __launch_bounds__(256, 1) void attn_kernel(
    const float* __restrict__ x, const float* __restrict__ gamma,
    float* __restrict__ out)
{
    extern __shared__ float sm[];
    float* Qs   = sm;                    // [128][36] n-major (A: row=n, col=d)
    float* Ks   = Qs + 128 * QS_S;       // [32][72]  d-major (B: row=d, col=m)
    float* Vs   = Ks + 32 * KS_S;        // [256][68] c-major (A: row=c, col=m)
    float* Ps   = Vs + 256 * VS_S;       // [64][136] m-major (B: row=m, col=n)
    float* alph = Ps + 64 * PS_S;        // [128]
    float* lrec = alph + 128;            // [128]

    const unsigned* Qu = (const unsigned*)Qs;
    const unsigned* Ku = (const unsigned*)Ks;
    const unsigned* Vu = (const unsigned*)Vs;
    const unsigned* Pu = (const unsigned*)Ps;

    int t = threadIdx.x;
    int w = t >> 5, lane = t & 31;
    int g = lane >> 2, t4 = lane & 3;
    int wr = w >> 1, wc = w & 1;
    int b = blockIdx.y;
    int n0 = blockIdx.x * 128;

    const float* qb = g_q + ((size_t)b * C8D) * NPIX;
    const float* kb = g_k + ((size_t)b * C8D) * NPIX;
    const float* vb = g_v + ((size_t)b * CIN) * NPIX;

    // Q tile load+transpose: [d][n] -> Qs[n][d]
#pragma unroll
    for (int i = 0; i < 16; i++) {
        int idx = t + 256 * i;
        int d = idx >> 7, n = idx & 127;
        Qs[n * QS_S + d] = qb[(size_t)d * NPIX + n0 + n];
    }

    float O[4][8][4];
#pragma unroll
    for (int rf = 0; rf < 4; rf++)
#pragma unroll
        for (int cf = 0; cf < 8; cf++)
#pragma unroll
            for (int r = 0; r < 4; r++) O[rf][cf][r] = 0.0f;

    float mr0 = -INFINITY, mr1 = -INFINITY, lr0 = 0.0f, lr1 = 0.0f;
    const int rS0 = 16 * w + g;      // S-phase row (query) owned by this thread
    const int rS1 = rS0 + 8;

    for (int mt = 0; mt < 64; mt++) {
        int m0 = mt * 64;
        // K tile [32][64]
#pragma unroll
        for (int i = 0; i < 2; i++) {
            int idx = t + 256 * i;
            int d = idx >> 4, m4 = (idx & 15) * 4;
            *(float4*)&Ks[d * KS_S + m4] = *(const float4*)&kb[(size_t)d * NPIX + m0 + m4];
        }
        // V tile [256][64]
#pragma unroll
        for (int i = 0; i < 16; i++) {
            int idx = t + 256 * i;
            int c = idx >> 4, m4 = (idx & 15) * 4;
            *(float4*)&Vs[c * VS_S + m4] = *(const float4*)&vb[(size_t)c * NPIX + m0 + m4];
        }
        __syncthreads();

        // ---- S = Q Kt : warp rows 16w..16w+15, cols 0..63 ----
        float S[8][4];
#pragma unroll
        for (int j = 0; j < 8; j++)
#pragma unroll
            for (int r = 0; r < 4; r++) S[j][r] = 0.0f;

#pragma unroll
        for (int ks = 0; ks < 4; ks++) {
            int kk = 8 * ks;
            unsigned a[4];
            a[0] = Qu[rS0 * QS_S + kk + t4];
            a[1] = Qu[rS1 * QS_S + kk + t4];
            a[2] = Qu[rS0 * QS_S + kk + t4 + 4];
            a[3] = Qu[rS1 * QS_S + kk + t4 + 4];
#pragma unroll
            for (int j = 0; j < 8; j++) {
                unsigned bfr[2];
                bfr[0] = Ku[(kk + t4)     * KS_S + 8 * j + g];
                bfr[1] = Ku[(kk + t4 + 4) * KS_S + 8 * j + g];
                mma_tf32(S[j], a, bfr);
            }
        }

        // ---- online softmax (rows rS0, rS1; 4 lanes per row) ----
        float mx0 = -INFINITY, mx1 = -INFINITY;
#pragma unroll
        for (int j = 0; j < 8; j++) {
            mx0 = fmaxf(mx0, fmaxf(S[j][0], S[j][1]));
            mx1 = fmaxf(mx1, fmaxf(S[j][2], S[j][3]));
        }
        mx0 = fmaxf(mx0, __shfl_xor_sync(0xffffffffu, mx0, 1));
        mx0 = fmaxf(mx0, __shfl_xor_sync(0xffffffffu, mx0, 2));
        mx1 = fmaxf(mx1, __shfl_xor_sync(0xffffffffu, mx1, 1));
        mx1 = fmaxf(mx1, __shfl_xor_sync(0xffffffffu, mx1, 2));
        float mn0 = fmaxf(mr0, mx0);
        float mn1 = fmaxf(mr1, mx1);
        float al0 = __expf(mr0 - mn0);
        float al1 = __expf(mr1 - mn1);
        mr0 = mn0; mr1 = mn1;

        float sum0 = 0.0f, sum1 = 0.0f;
#pragma unroll
        for (int j = 0; j < 8; j++) {
            int m = 8 * j + 2 * t4;
            float p00 = __expf(S[j][0] - mn0);
            float p01 = __expf(S[j][1] - mn0);
            float p10 = __expf(S[j][2] - mn1);
            float p11 = __expf(S[j][3] - mn1);
            sum0 += p00 + p01;
            sum1 += p10 + p11;
            Ps[ m      * PS_S + rS0] = __uint_as_float(f2tf32(p00));
            Ps[(m + 1) * PS_S + rS0] = __uint_as_float(f2tf32(p01));
            Ps[ m      * PS_S + rS1] = __uint_as_float(f2tf32(p10));
            Ps[(m + 1) * PS_S + rS1] = __uint_as_float(f2tf32(p11));
        }
        sum0 += __shfl_xor_sync(0xffffffffu, sum0, 1);
        sum0 += __shfl_xor_sync(0xffffffffu, sum0, 2);
        sum1 += __shfl_xor_sync(0xffffffffu, sum1, 1);
        sum1 += __shfl_xor_sync(0xffffffffu, sum1, 2);
        lr0 = lr0 * al0 + sum0;
        lr1 = lr1 * al1 + sum1;
        if (t4 == 0) { alph[rS0] = al0; alph[rS1] = al1; }
        __syncthreads();

        // ---- O rescale by alpha[n] ----
#pragma unroll
        for (int cf = 0; cf < 8; cf++) {
            int nl = 64 * wc + 8 * cf + 2 * t4;
            float alo = alph[nl];
            float ahi = alph[nl + 1];
#pragma unroll
            for (int rf = 0; rf < 4; rf++) {
                O[rf][cf][0] *= alo; O[rf][cf][1] *= ahi;
                O[rf][cf][2] *= alo; O[rf][cf][3] *= ahi;
            }
        }

        // ---- O += V Pt : warp c rows 64wr + 16rf..., n cols 64wc + 8cf... ----
#pragma unroll
        for (int ks = 0; ks < 8; ks++) {
            int kk = 8 * ks;
            unsigned av[4][4];
#pragma unroll
            for (int rf = 0; rf < 4; rf++) {
                int c0 = 64 * wr + 16 * rf + g;
                av[rf][0] = Vu[ c0      * VS_S + kk + t4];
                av[rf][1] = Vu[(c0 + 8) * VS_S + kk + t4];
                av[rf][2] = Vu[ c0      * VS_S + kk + t4 + 4];
                av[rf][3] = Vu[(c0 + 8) * VS_S + kk + t4 + 4];
            }
#pragma unroll
            for (int cf = 0; cf < 8; cf++) {
                unsigned bfr[2];
                bfr[0] = Pu[(kk + t4)     * PS_S + 64 * wc + 8 * cf + g];
                bfr[1] = Pu[(kk + t4 + 4) * PS_S + 64 * wc + 8 * cf + g];
#pragma unroll
                for (int rf = 0; rf < 4; rf++)
                    mma_tf32(O[rf][cf], av[rf], bfr);
            }
        }
        __syncthreads();
    }

    // ---- epilogue: out = gamma * O / l + x ----
    if (t4 == 0) {
        lrec[rS0] = 1.0f / lr0;
        lrec[rS1] = 1.0f / lr1;
    }
    __syncthreads();

    float gm = gamma[0];
#pragma unroll
    for (int rf = 0; rf < 4; rf++) {
#pragma unroll
        for (int cf = 0; cf < 8; cf++) {
            int c  = 64 * wr + 16 * rf + g;
            int nl = 64 * wc + 8 * cf + 2 * t4;
            float il0 = lrec[nl];
            float il1 = lrec[nl + 1];
            size_t idx = ((size_t)b * CIN + c) * NPIX + n0 + nl;
            float2 xv = *(const float2*)&x[idx];
            float2 ov;
            ov.x = gm * (O[rf][cf][0] * il0) + xv.x;
            ov.y = gm * (O[rf][cf][1] * il1) + xv.y;
            *(float2*)&out[idx] = ov;
            size_t idx2 = idx + 8 * (size_t)NPIX;
            float2 xv2 = *(const float2*)&x[idx2];
            float2 ov2;
            ov2.x = gm * (O[rf][cf][2] * il0) + xv2.x;
            ov2.y = gm * (O[rf][cf][3] * il1) + xv2.y;
            *(float2*)&out[idx2] = ov2;
        }
    }
}

// ---------------------------------------------------------------------------
extern "C" void kernel_launch(void* const* d_in, const int* in_sizes, int n_in,
                              void* d_out, int out_size)
{
    (void)in_sizes; (void)n_in; (void)out_size;
    const float* x     = (const float*)d_in[0];
    const float* Wq    = (const float*)d_in[1];
    const float* bq    = (const float*)d_in[2];
    const float* Wk    = (const float*)d_in[3];
    const float* bk    = (const float*)d_in[4];
    const float* Wv    = (const float*)d_in[5];
    const float* bv    = (const float*)d_in[6];
    const float* gamma = (const float*)d_in[7];
    float* out = (float*)d_out;

    const int ATTN_SMEM = (128 * QS_S + 32 * KS_S + 256 * VS_S + 64 * PS_S + 256) * 4;

    cudaFuncSetAttribute(attn_kernel,
                         cudaFuncAttributeMaxDynamicSharedMemorySize, ATTN_SMEM);

    proj_kernel<<<dim3(NPIX / 128, 5, NB), 256>>>(x, Wq, bq, Wk, bk, Wv, bv);
    attn_kernel<<<dim3(NPIX / 128, NB), 256, ATTN_SMEM>>>(x, gamma, out);
}

// round 5
// speedup vs baseline: 7.0433x; 1.6494x over previous
#include <cuda_runtime.h>
#include <cuda_bf16.h>
#include <math.h>

#define NB   4
#define CIN  256
#define C8D  32
#define NPIX 4096

// Scratch (device globals: allocation-free per harness rules).
__device__ float g_q[NB * C8D * NPIX];          // tf32-rounded
__device__ float g_k[NB * C8D * NPIX];          // tf32-rounded
__device__ __nv_bfloat16 g_v[NB * CIN * NPIX];  // bf16

__device__ __forceinline__ unsigned f2tf32(float x) {
    unsigned u;
    asm("cvt.rna.tf32.f32 %0, %1;" : "=r"(u) : "f"(x));
    return u;
}

__device__ __forceinline__ void mma_tf32(float* d, const unsigned* a, const unsigned* b) {
    asm volatile(
        "mma.sync.aligned.m16n8k8.row.col.f32.tf32.tf32.f32 "
        "{%0,%1,%2,%3}, {%4,%5,%6,%7}, {%8,%9}, {%0,%1,%2,%3};"
        : "+f"(d[0]), "+f"(d[1]), "+f"(d[2]), "+f"(d[3])
        : "r"(a[0]), "r"(a[1]), "r"(a[2]), "r"(a[3]), "r"(b[0]), "r"(b[1]));
}

__device__ __forceinline__ void mma_bf16(float* d, const unsigned* a, unsigned b0, unsigned b1) {
    asm volatile(
        "mma.sync.aligned.m16n8k16.row.col.f32.bf16.bf16.f32 "
        "{%0,%1,%2,%3}, {%4,%5,%6,%7}, {%8,%9}, {%0,%1,%2,%3};"
        : "+f"(d[0]), "+f"(d[1]), "+f"(d[2]), "+f"(d[3])
        : "r"(a[0]), "r"(a[1]), "r"(a[2]), "r"(a[3]), "r"(b0), "r"(b1));
}

__device__ __forceinline__ unsigned pack_bf16(float lo, float hi) {
    __nv_bfloat162 p = __floats2bfloat162_rn(lo, hi);
    return *(unsigned*)&p;
}

__device__ __forceinline__ void cp16(unsigned dst, const void* src) {
    asm volatile("cp.async.cg.shared.global [%0], [%1], 16;\n" :: "r"(dst), "l"(src));
}

// ---------------------------------------------------------------------------
// Merged projection: [Wv(256); Wq(32); Wk(32)] @ x[b].
// V rows -> g_v (bf16); q/k rows -> g_q/g_k (tf32-rounded fp32).
// grid (32, 5, 4), block 256.
// ---------------------------------------------------------------------------
__global__ __launch_bounds__(256) void proj_kernel(
    const float* __restrict__ x,
    const float* __restrict__ Wq, const float* __restrict__ bq,
    const float* __restrict__ Wk, const float* __restrict__ bk,
    const float* __restrict__ Wv, const float* __restrict__ bv)
{
    __shared__ float As[16][68];
    __shared__ float Bs[16][128];

    int b  = blockIdx.z;
    int r0 = blockIdx.y * 64;
    int n0 = blockIdx.x * 128;
    int t  = threadIdx.x;
    int tx = t & 31, ty = t >> 5;
    const float* xb = x + ((size_t)b * CIN) * NPIX;

    float acc[8][4];
#pragma unroll
    for (int i = 0; i < 8; i++)
#pragma unroll
        for (int j = 0; j < 4; j++) acc[i][j] = 0.0f;

    for (int k0 = 0; k0 < 256; k0 += 16) {
        {
            int row = t >> 2;
            int kc  = (t & 3) * 4;
            int gr  = r0 + row;
            const float* wp = (gr < 256) ? (Wv + (size_t)gr * 256)
                            : (gr < 288) ? (Wq + (size_t)(gr - 256) * 256)
                                         : (Wk + (size_t)(gr - 288) * 256);
            float4 w = *(const float4*)(wp + k0 + kc);
            As[kc + 0][row] = w.x; As[kc + 1][row] = w.y;
            As[kc + 2][row] = w.z; As[kc + 3][row] = w.w;
        }
#pragma unroll
        for (int i = 0; i < 2; i++) {
            int idx = t + 256 * i;
            int kc = idx >> 5, j = idx & 31;
            *(float4*)&Bs[kc][j * 4] =
                *(const float4*)&xb[(size_t)(k0 + kc) * NPIX + n0 + j * 4];
        }
        __syncthreads();

#pragma unroll
        for (int kc = 0; kc < 16; kc++) {
            float a[8];
#pragma unroll
            for (int i = 0; i < 8; i++) a[i] = As[kc][ty * 8 + i];
            float4 bb = *(const float4*)&Bs[kc][tx * 4];
#pragma unroll
            for (int i = 0; i < 8; i++) {
                acc[i][0] += a[i] * bb.x;
                acc[i][1] += a[i] * bb.y;
                acc[i][2] += a[i] * bb.z;
                acc[i][3] += a[i] * bb.w;
            }
        }
        __syncthreads();
    }

#pragma unroll
    for (int i = 0; i < 8; i++) {
        int gr = r0 + ty * 8 + i;
        if (gr < 256) {
            float bias = bv[gr];
            __nv_bfloat16* op = g_v + ((size_t)b * CIN + gr) * NPIX;
            unsigned u0 = pack_bf16(acc[i][0] + bias, acc[i][1] + bias);
            unsigned u1 = pack_bf16(acc[i][2] + bias, acc[i][3] + bias);
            *(uint2*)&op[n0 + tx * 4] = make_uint2(u0, u1);
        } else {
            float bias;
            float* op;
            if (gr < 288) { bias = bq[gr - 256]; op = g_q + ((size_t)b * C8D + gr - 256) * NPIX; }
            else          { bias = bk[gr - 288]; op = g_k + ((size_t)b * C8D + gr - 288) * NPIX; }
            float4 o;
            o.x = __uint_as_float(f2tf32(acc[i][0] + bias));
            o.y = __uint_as_float(f2tf32(acc[i][1] + bias));
            o.z = __uint_as_float(f2tf32(acc[i][2] + bias));
            o.w = __uint_as_float(f2tf32(acc[i][3] + bias));
            *(float4*)&op[n0 + tx * 4] = o;
        }
    }
}

// ---------------------------------------------------------------------------
// Flash attention: S = QKt in tf32 mma, PV in bf16 mma with P in registers.
// BQ=128/CTA, BK=64/iter, grid (32,4)=128 CTAs (one wave), block 256.
// Warp w owns query rows [16w,16w+16) for BOTH S and O' (n-major output):
// softmax + rescale + l are warp-local registers; no P/alpha SMEM.
// K/V tiles double-buffered via cp.async; one barrier per iteration.
// ---------------------------------------------------------------------------
#define QS_S 36   // floats
#define KS_S 72   // floats
#define VS_S 72   // bf16 units

__global__ __launch_bounds__(256, 1) void attn_kernel(
    const float* __restrict__ x, const float* __restrict__ gamma,
    float* __restrict__ out)
{
    extern __shared__ float smf[];
    float* Qs = smf;                                   // [128][36] fp32
    float* Ks = smf + 128 * QS_S;                      // 2 x [32][72] fp32
    __nv_bfloat16* Vs = (__nv_bfloat16*)(smf + 128 * QS_S + 2 * 32 * KS_S); // 2 x [256][72] bf16

    const unsigned* Qu = (const unsigned*)Qs;

    unsigned sm_base = (unsigned)__cvta_generic_to_shared(smf);
    unsigned ks_base = sm_base + 128 * QS_S * 4;
    unsigned vs_base = ks_base + 2 * 32 * KS_S * 4;

    int t = threadIdx.x;
    int w = t >> 5, lane = t & 31;
    int g = lane >> 2, t4 = lane & 3;
    int b = blockIdx.y;
    int n0 = blockIdx.x * 128;

    const float* qb = g_q + ((size_t)b * C8D) * NPIX;
    const float* kb = g_k + ((size_t)b * C8D) * NPIX;
    const __nv_bfloat16* vbb = g_v + ((size_t)b * CIN) * NPIX;

    // ---- stage copy: K [32][64] fp32 + V [256][64] bf16 into buffer s ----
    auto issue_stage = [&](int mt, int s) {
        int m0 = mt * 64;
#pragma unroll
        for (int i = 0; i < 2; i++) {            // K: 512 x 16B
            int flat = t + 256 * i;
            int d = flat >> 4, seg = flat & 15;
            cp16(ks_base + (unsigned)(s * 32 * KS_S + d * KS_S + seg * 4) * 4,
                 kb + (size_t)d * NPIX + m0 + seg * 4);
        }
#pragma unroll
        for (int i = 0; i < 8; i++) {            // V: 2048 x 16B
            int flat = t + 256 * i;
            int c = flat >> 3, seg = flat & 7;
            cp16(vs_base + (unsigned)(s * 256 * VS_S + c * VS_S + seg * 8) * 2,
                 vbb + (size_t)c * NPIX + m0 + seg * 8);
        }
        asm volatile("cp.async.commit_group;\n");
    };

    issue_stage(0, 0);

    // Q tile load+transpose: [d][n] -> Qs[n][d]
#pragma unroll
    for (int i = 0; i < 16; i++) {
        int idx = t + 256 * i;
        int d = idx >> 7, n = idx & 127;
        Qs[n * QS_S + d] = qb[(size_t)d * NPIX + n0 + n];
    }
    __syncthreads();

    const int rS0 = 16 * w + g;
    const int rS1 = rS0 + 8;

    // Q fragments (loop-invariant)
    unsigned qa[4][4];
#pragma unroll
    for (int ks = 0; ks < 4; ks++) {
        qa[ks][0] = Qu[rS0 * QS_S + 8 * ks + t4];
        qa[ks][1] = Qu[rS1 * QS_S + 8 * ks + t4];
        qa[ks][2] = Qu[rS0 * QS_S + 8 * ks + t4 + 4];
        qa[ks][3] = Qu[rS1 * QS_S + 8 * ks + t4 + 4];
    }

    float O[32][4];
#pragma unroll
    for (int jc = 0; jc < 32; jc++)
#pragma unroll
        for (int r = 0; r < 4; r++) O[jc][r] = 0.0f;

    float mr0 = -INFINITY, mr1 = -INFINITY, lr0 = 0.0f, lr1 = 0.0f;

    for (int mt = 0; mt < 64; mt++) {
        asm volatile("cp.async.wait_group 0;\n");
        __syncthreads();
        if (mt + 1 < 64) issue_stage(mt + 1, (mt + 1) & 1);

        int s = mt & 1;
        const unsigned* Ku = (const unsigned*)(Ks + s * 32 * KS_S);
        const unsigned* Vu = (const unsigned*)(Vs + s * 256 * VS_S);

        // ---- S = Q Kt (tf32) : rows rS0/rS1, cols 0..63 ----
        float S[8][4];
#pragma unroll
        for (int j = 0; j < 8; j++)
#pragma unroll
            for (int r = 0; r < 4; r++) S[j][r] = 0.0f;

#pragma unroll
        for (int ks = 0; ks < 4; ks++) {
            int kk = 8 * ks;
#pragma unroll
            for (int j = 0; j < 8; j++) {
                unsigned bfr[2];
                bfr[0] = Ku[(kk + t4)     * KS_S + 8 * j + g];
                bfr[1] = Ku[(kk + t4 + 4) * KS_S + 8 * j + g];
                mma_tf32(S[j], qa[ks], bfr);
            }
        }

        // ---- online softmax (warp-local; quad = 4 lanes per row) ----
        float mx0 = -INFINITY, mx1 = -INFINITY;
#pragma unroll
        for (int j = 0; j < 8; j++) {
            mx0 = fmaxf(mx0, fmaxf(S[j][0], S[j][1]));
            mx1 = fmaxf(mx1, fmaxf(S[j][2], S[j][3]));
        }
        mx0 = fmaxf(mx0, __shfl_xor_sync(0xffffffffu, mx0, 1));
        mx0 = fmaxf(mx0, __shfl_xor_sync(0xffffffffu, mx0, 2));
        mx1 = fmaxf(mx1, __shfl_xor_sync(0xffffffffu, mx1, 1));
        mx1 = fmaxf(mx1, __shfl_xor_sync(0xffffffffu, mx1, 2));
        float mn0 = fmaxf(mr0, mx0);
        float mn1 = fmaxf(mr1, mx1);
        float al0 = __expf(mr0 - mn0);
        float al1 = __expf(mr1 - mn1);
        mr0 = mn0; mr1 = mn1;

        unsigned pa[4][4];   // bf16 A-fragments of P
        float sum0 = 0.0f, sum1 = 0.0f;
#pragma unroll
        for (int j = 0; j < 8; j++) {
            float p00 = __expf(S[j][0] - mn0);
            float p01 = __expf(S[j][1] - mn0);
            float p10 = __expf(S[j][2] - mn1);
            float p11 = __expf(S[j][3] - mn1);
            sum0 += p00 + p01;
            sum1 += p10 + p11;
            int kc = j >> 1;
            if ((j & 1) == 0) {
                pa[kc][0] = pack_bf16(p00, p01);
                pa[kc][1] = pack_bf16(p10, p11);
            } else {
                pa[kc][2] = pack_bf16(p00, p01);
                pa[kc][3] = pack_bf16(p10, p11);
            }
        }
        sum0 += __shfl_xor_sync(0xffffffffu, sum0, 1);
        sum0 += __shfl_xor_sync(0xffffffffu, sum0, 2);
        sum1 += __shfl_xor_sync(0xffffffffu, sum1, 1);
        sum1 += __shfl_xor_sync(0xffffffffu, sum1, 2);
        lr0 = lr0 * al0 + sum0;
        lr1 = lr1 * al1 + sum1;

        // ---- O rescale (register-local) ----
#pragma unroll
        for (int jc = 0; jc < 32; jc++) {
            O[jc][0] *= al0; O[jc][1] *= al0;
            O[jc][2] *= al1; O[jc][3] *= al1;
        }

        // ---- O'[n][c] += P[n][m] V[c][m]^T  (bf16 mma, k=16 per step) ----
#pragma unroll
        for (int kc = 0; kc < 4; kc++) {
#pragma unroll
            for (int jc = 0; jc < 32; jc++) {
                int base = (8 * jc + g) * (VS_S / 2) + 8 * kc + t4;
                unsigned b0 = Vu[base];
                unsigned b1 = Vu[base + 4];
                mma_bf16(O[jc], pa[kc], b0, b1);
            }
        }
    }

    // ---- epilogue: out = gamma * O / l + x (all register-local) ----
    float il0 = 1.0f / lr0;
    float il1 = 1.0f / lr1;
    float gm = gamma[0];
    int n = n0 + 16 * w + g;
#pragma unroll
    for (int jc = 0; jc < 32; jc++) {
        int c = 8 * jc + 2 * t4;
        size_t i00 = ((size_t)(b * CIN + c)) * NPIX + n;
        out[i00]            = gm * (O[jc][0] * il0) + x[i00];
        out[i00 + NPIX]     = gm * (O[jc][1] * il0) + x[i00 + NPIX];
        out[i00 + 8]        = gm * (O[jc][2] * il1) + x[i00 + 8];
        out[i00 + NPIX + 8] = gm * (O[jc][3] * il1) + x[i00 + NPIX + 8];
    }
}

// ---------------------------------------------------------------------------
extern "C" void kernel_launch(void* const* d_in, const int* in_sizes, int n_in,
                              void* d_out, int out_size)
{
    (void)in_sizes; (void)n_in; (void)out_size;
    const float* x     = (const float*)d_in[0];
    const float* Wq    = (const float*)d_in[1];
    const float* bq    = (const float*)d_in[2];
    const float* Wk    = (const float*)d_in[3];
    const float* bk    = (const float*)d_in[4];
    const float* Wv    = (const float*)d_in[5];
    const float* bv    = (const float*)d_in[6];
    const float* gamma = (const float*)d_in[7];
    float* out = (float*)d_out;

    const int ATTN_SMEM = 128 * QS_S * 4 + 2 * 32 * KS_S * 4 + 2 * 256 * VS_S * 2; // 110592

    cudaFuncSetAttribute(attn_kernel,
                         cudaFuncAttributeMaxDynamicSharedMemorySize, ATTN_SMEM);

    proj_kernel<<<dim3(NPIX / 128, 5, NB), 256>>>(x, Wq, bq, Wk, bk, Wv, bv);
    attn_kernel<<<dim3(NPIX / 128, NB), 256, ATTN_SMEM>>>(x, gamma, out);
}